// round 2
// baseline (speedup 1.0000x reference)
#include <cuda_runtime.h>
#include <cuda_bf16.h>
#include <cstdint>
#include <cstddef>

#define DINL __device__ __forceinline__

// ---------------- problem constants ----------------
static constexpr int M_TOTAL = 8192;     // 4 * 2048
static constexpr int N_TOTAL = 11008;
static constexpr int K_TOTAL = 4096;
static constexpr int PACKED  = K_TOTAL / 2;
static constexpr int NGROUPS = 32;

static constexpr int TILE_M = 128;
static constexpr int TILE_N = 128;
static constexpr int TILE_K = 32;
static constexpr int STAGES = 4;
static constexpr int N_ITERS = K_TOTAL / TILE_K;      // 128
static constexpr int THREADS = 256;

static constexpr int NUM_MT = M_TOTAL / TILE_M;       // 64
static constexpr int NUM_NT = N_TOTAL / TILE_N;       // 86
static constexpr int GRID   = NUM_MT * NUM_NT;        // 5504
static constexpr int GROUP_M = 12;                    // supergroup height (m-tiles)

static constexpr int STAGE_WORDS = TILE_M * TILE_K;   // 4096 floats = 16KB
static constexpr int SMEM_BYTES  = 2 * STAGES * STAGE_WORDS * 4;   // 128KB

// ---------------- persistent scratch ----------------
__device__ float g_W[(size_t)N_TOTAL * K_TOTAL];   // dequantized, tf32-rounded
__device__ float g_X[(size_t)M_TOTAL * K_TOTAL];   // tf32-rounded activations

// ---------------- helpers ----------------
DINL uint32_t smem_u32(const void* p) {
    uint32_t a;
    asm("{ .reg .u64 t; cvta.to.shared.u64 t, %1; cvt.u32.u64 %0, t; }" : "=r"(a) : "l"(p));
    return a;
}
DINL float rna_tf32(float x) {
    float r; asm("cvt.rna.tf32.f32 %0, %1;" : "=f"(r) : "f"(x)); return r;
}
DINL void cp_async16(uint32_t dst, const void* src) {
    asm volatile("cp.async.cg.shared.global [%0], [%1], 16;" :: "r"(dst), "l"(src) : "memory");
}
DINL void cp_commit() { asm volatile("cp.async.commit_group;" ::: "memory"); }

DINL void mma_tf32(float* d, const uint32_t* a, const uint32_t* b) {
    asm volatile(
        "mma.sync.aligned.m16n8k8.row.col.f32.tf32.tf32.f32 "
        "{%0,%1,%2,%3}, {%4,%5,%6,%7}, {%8,%9}, {%0,%1,%2,%3};"
        : "+f"(d[0]), "+f"(d[1]), "+f"(d[2]), "+f"(d[3])
        : "r"(a[0]), "r"(a[1]), "r"(a[2]), "r"(a[3]), "r"(b[0]), "r"(b[1]));
}

// ---------------- prep kernels ----------------
__global__ void dequant_kernel(const int* __restrict__ wp,
                               const float* __restrict__ scale,
                               const float* __restrict__ zp) {
    size_t idx = (size_t)blockIdx.x * blockDim.x + threadIdx.x;   // over O * PACKED
    int o = (int)(idx >> 11);
    int p = (int)(idx & 2047);
    int v  = wp[idx];
    int hi = (v >> 4) & 15;          // high nibble first
    int lo = v & 15;
    int g  = p >> 6;
    float s = scale[o * NGROUPS + g];
    float z = zp[o * NGROUPS + g];
    float2 out;
    out.x = rna_tf32(((float)hi - z) * s);
    out.y = rna_tf32(((float)lo - z) * s);
    *(float2*)(g_W + (size_t)o * K_TOTAL + 2 * p) = out;
}

__global__ void xprep_kernel(const float* __restrict__ x) {
    size_t i = (size_t)blockIdx.x * blockDim.x + threadIdx.x;     // over M*K/4
    float4 v = ((const float4*)x)[i];
    v.x = rna_tf32(v.x); v.y = rna_tf32(v.y);
    v.z = rna_tf32(v.z); v.w = rna_tf32(v.w);
    ((float4*)g_X)[i] = v;
}

// ---------------- TF32 mma.sync GEMM ----------------
__global__ void __launch_bounds__(THREADS)
gemm_kernel(const float* __restrict__ bias, float* __restrict__ out) {
    extern __shared__ float smem[];
    float* As = smem;                           // [STAGES][4096]
    float* Bs = smem + STAGES * STAGE_WORDS;    // [STAGES][4096]
    const uint32_t abase = smem_u32(As);
    const uint32_t bbase = smem_u32(Bs);

    const int tid  = threadIdx.x;
    const int lane = tid & 31;
    const int wid  = tid >> 5;
    const int wm   = (wid & 3) * 32;    // warp M offset in tile
    const int wn   = (wid >> 2) * 64;   // warp N offset in tile

    // ---- supergroup rasterization (12 m-tiles per group, m fastest) ----
    int bid = blockIdx.x;
    int group = bid / (GROUP_M * NUM_NT);
    int rem   = bid % (GROUP_M * NUM_NT);
    int gm    = NUM_MT - group * GROUP_M;
    if (gm > GROUP_M) gm = GROUP_M;
    const int m0 = (group * GROUP_M + rem % gm) * TILE_M;
    const int n0 = (rem / gm) * TILE_N;

    // ---- cp.async slots: 1024 16B-chunks per tile -> 4 per thread ----
    const float* aS[4]; const float* bS[4]; uint32_t aD[4];
    #pragma unroll
    for (int i = 0; i < 4; i++) {
        int cid = tid + i * THREADS;        // 0..1023
        int r  = cid >> 3;                  // row 0..127
        int ch = cid & 7;                   // 16B-chunk within row
        aS[i] = g_X + (size_t)(m0 + r) * K_TOTAL + ch * 4;
        bS[i] = g_W + (size_t)(n0 + r) * K_TOTAL + ch * 4;
        aD[i] = (uint32_t)(r * TILE_K + 4 * (ch ^ (r & 7))) * 4;  // byte off, swizzled
    }

    auto load_stage = [&](int pit) {
        const int s = pit & (STAGES - 1);
        const int kb = pit * TILE_K;
        const uint32_t ab = abase + s * STAGE_WORDS * 4;
        const uint32_t bb = bbase + s * STAGE_WORDS * 4;
        #pragma unroll
        for (int i = 0; i < 4; i++) cp_async16(ab + aD[i], aS[i] + kb);
        #pragma unroll
        for (int i = 0; i < 4; i++) cp_async16(bb + aD[i], bS[i] + kb);
    };

    float acc[2][8][4];
    #pragma unroll
    for (int mt = 0; mt < 2; mt++)
        #pragma unroll
        for (int nt = 0; nt < 8; nt++)
            #pragma unroll
            for (int c = 0; c < 4; c++) acc[mt][nt][c] = 0.f;

    // prologue: stages 0..2
    #pragma unroll
    for (int s = 0; s < STAGES - 1; s++) { load_stage(s); cp_commit(); }

    const int tig = lane & 3;       // thread in group
    const int gid = lane >> 2;      // group id (row within 8)

    for (int it = 0; it < N_ITERS; ++it) {
        const int pit = it + STAGES - 1;
        if (pit < N_ITERS) load_stage(pit);
        cp_commit();
        asm volatile("cp.async.wait_group %0;" :: "n"(STAGES - 1) : "memory");
        __syncthreads();

        const int s = it & (STAGES - 1);
        const float* A = As + s * STAGE_WORDS;
        const float* B = Bs + s * STAGE_WORDS;

        #pragma unroll
        for (int kk = 0; kk < 4; kk++) {
            const int k0 = kk * 8;
            uint32_t afr[2][4], bfr[8][2];
            #pragma unroll
            for (int mt = 0; mt < 2; mt++) {
                int r  = wm + mt * 16 + gid;
                int cs = (k0 + tig) ^ ((r & 7) << 2);      // swizzled col
                const uint32_t* Ar = (const uint32_t*)(A + r * TILE_K);
                afr[mt][0] = Ar[cs];
                afr[mt][1] = Ar[cs + 8 * TILE_K];          // row + 8
                afr[mt][2] = Ar[cs ^ 4];                   // col + 4
                afr[mt][3] = Ar[(cs ^ 4) + 8 * TILE_K];
            }
            #pragma unroll
            for (int nt = 0; nt < 8; nt++) {
                int r  = wn + nt * 8 + gid;
                int cs = (k0 + tig) ^ ((r & 7) << 2);
                const uint32_t* Br = (const uint32_t*)(B + r * TILE_K);
                bfr[nt][0] = Br[cs];
                bfr[nt][1] = Br[cs ^ 4];
            }
            #pragma unroll
            for (int mt = 0; mt < 2; mt++)
                #pragma unroll
                for (int nt = 0; nt < 8; nt++)
                    mma_tf32(acc[mt][nt], afr[mt], bfr[nt]);
        }
        __syncthreads();
    }

    // ---- epilogue: direct gmem store + bias ----
    #pragma unroll
    for (int nt = 0; nt < 8; nt++) {
        const int n = n0 + wn + nt * 8 + tig * 2;
        const float bv0 = __ldg(bias + n);
        const float bv1 = __ldg(bias + n + 1);
        #pragma unroll
        for (int mt = 0; mt < 2; mt++) {
            const int m = m0 + wm + mt * 16 + gid;
            float2 v0 = { acc[mt][nt][0] + bv0, acc[mt][nt][1] + bv1 };
            float2 v1 = { acc[mt][nt][2] + bv0, acc[mt][nt][3] + bv1 };
            *(float2*)(out + (size_t)m * N_TOTAL + n) = v0;
            *(float2*)(out + (size_t)(m + 8) * N_TOTAL + n) = v1;
        }
    }
}

// ---------------- launch ----------------
extern "C" void kernel_launch(void* const* d_in, const int* in_sizes, int n_in,
                              void* d_out, int out_size) {
    const float* x     = (const float*)d_in[0];
    const int*   wp    = (const int*)d_in[1];
    const float* scale = (const float*)d_in[2];
    const float* zp    = (const float*)d_in[3];
    const float* bias  = (const float*)d_in[4];
    float* out = (float*)d_out;

    static bool attr_set = false;
    cudaFuncSetAttribute(gemm_kernel,
                         cudaFuncAttributeMaxDynamicSharedMemorySize, SMEM_BYTES);
    (void)attr_set;

    dequant_kernel<<<(N_TOTAL * PACKED) / 256, 256>>>(wp, scale, zp);
    xprep_kernel<<<(M_TOTAL * K_TOTAL / 4) / 256, 256>>>(x);
    gemm_kernel<<<GRID, THREADS, SMEM_BYTES>>>(bias, out);
}

// round 6
// speedup vs baseline: 1.1093x; 1.1093x over previous
#include <cuda_runtime.h>
#include <cuda_bf16.h>
#include <cstdint>
#include <cstddef>

#define DINL __device__ __forceinline__

// ---------------- problem constants ----------------
static constexpr int M_TOTAL = 8192;
static constexpr int N_TOTAL = 11008;
static constexpr int K_TOTAL = 4096;
static constexpr int PACKED  = K_TOTAL / 2;
static constexpr int NGROUPS = 32;

static constexpr int TILE_M = 128;
static constexpr int TILE_N = 256;
static constexpr int TILE_K = 32;
static constexpr int STAGES = 4;
static constexpr int N_ITERS = K_TOTAL / TILE_K;      // 128
static constexpr int THREADS = 256;

static constexpr int NUM_MT = M_TOTAL / TILE_M;       // 64
static constexpr int NUM_NT = N_TOTAL / TILE_N;       // 43
static constexpr int GRID   = NUM_MT * NUM_NT;        // 2752
static constexpr int GROUP_M = 12;

static constexpr int A_STAGE_W = TILE_M * TILE_K;     // 4096 words
static constexpr int B_STAGE_W = TILE_N * TILE_K;     // 8192 words
static constexpr int SMEM_BYTES = STAGES * (A_STAGE_W + B_STAGE_W) * 4;   // 196608

// ---------------- persistent scratch ----------------
__device__ float g_W[(size_t)N_TOTAL * K_TOTAL];
__device__ float g_X[(size_t)M_TOTAL * K_TOTAL];

// ---------------- helpers ----------------
DINL uint32_t smem_u32(const void* p) {
    uint32_t a;
    asm("{ .reg .u64 t; cvta.to.shared.u64 t, %1; cvt.u32.u64 %0, t; }" : "=r"(a) : "l"(p));
    return a;
}
DINL float rna_tf32(float x) {
    float r; asm("cvt.rna.tf32.f32 %0, %1;" : "=f"(r) : "f"(x)); return r;
}
DINL void cp_async16(uint32_t dst, const void* src) {
    asm volatile("cp.async.cg.shared.global [%0], [%1], 16;" :: "r"(dst), "l"(src) : "memory");
}
DINL void cp_commit() { asm volatile("cp.async.commit_group;" ::: "memory"); }

DINL void mma_tf32(float* d, const uint32_t* a, const uint32_t* b) {
    asm volatile(
        "mma.sync.aligned.m16n8k8.row.col.f32.tf32.tf32.f32 "
        "{%0,%1,%2,%3}, {%4,%5,%6,%7}, {%8,%9}, {%0,%1,%2,%3};"
        : "+f"(d[0]), "+f"(d[1]), "+f"(d[2]), "+f"(d[3])
        : "r"(a[0]), "r"(a[1]), "r"(a[2]), "r"(a[3]), "r"(b[0]), "r"(b[1]));
}

// ---------------- prep kernels ----------------
__global__ void dequant_kernel(const int* __restrict__ wp,
                               const float* __restrict__ scale,
                               const float* __restrict__ zp) {
    size_t idx = (size_t)blockIdx.x * blockDim.x + threadIdx.x;
    int o = (int)(idx >> 11);
    int p = (int)(idx & 2047);
    int v  = wp[idx];
    int hi = (v >> 4) & 15;
    int lo = v & 15;
    int g  = p >> 6;
    float s = scale[o * NGROUPS + g];
    float z = zp[o * NGROUPS + g];
    float2 out;
    out.x = rna_tf32(((float)hi - z) * s);
    out.y = rna_tf32(((float)lo - z) * s);
    *(float2*)(g_W + (size_t)o * K_TOTAL + 2 * p) = out;
}

__global__ void xprep_kernel(const float* __restrict__ x) {
    size_t i = (size_t)blockIdx.x * blockDim.x + threadIdx.x;
    float4 v = ((const float4*)x)[i];
    v.x = rna_tf32(v.x); v.y = rna_tf32(v.y);
    v.z = rna_tf32(v.z); v.w = rna_tf32(v.w);
    ((float4*)g_X)[i] = v;
}

// ---------------- TF32 mma.sync GEMM, 128x256 CTA, 64x64 warp ----------------
__global__ void __launch_bounds__(THREADS, 1)
gemm_kernel(const float* __restrict__ bias, float* __restrict__ out) {
    extern __shared__ float smem[];
    float* As = smem;                             // [STAGES][4096]
    float* Bs = smem + STAGES * A_STAGE_W;        // [STAGES][8192]

    const int tid  = threadIdx.x;
    const int lane = tid & 31;
    const int wid  = tid >> 5;
    const int wm   = (wid & 1) * 64;     // warp M offset (2 rows of warps)
    const int wn   = (wid >> 1) * 64;    // warp N offset (4 cols of warps)
    const int tig  = lane & 3;
    const int gid  = lane >> 2;

    // ---- supergroup rasterization ----
    int bid = blockIdx.x;
    int group = bid / (GROUP_M * NUM_NT);
    int rem   = bid % (GROUP_M * NUM_NT);
    int gm    = NUM_MT - group * GROUP_M;
    if (gm > GROUP_M) gm = GROUP_M;
    const int m0 = (group * GROUP_M + rem % gm) * TILE_M;
    const int n0 = (rem / gm) * TILE_N;

    // ---- cp.async addressing ----
    // A: 1024 16B-chunks (4/thread), B: 2048 (8/thread).
    // slot i covers row (tid>>3) + 32*i, chunk tid&7.
    const int lrow = tid >> 3;
    const int lch  = tid & 7;
    const float* aPtr = g_X + (size_t)(m0 + lrow) * K_TOTAL + lch * 4;
    const float* bPtr = g_W + (size_t)(n0 + lrow) * K_TOTAL + lch * 4;
    // swizzled smem word offset within a stage for slot 0 (row&7 invariant across slots)
    const uint32_t sOff = (uint32_t)(lrow * TILE_K + 4 * (lch ^ (lrow & 7))) * 4;  // bytes
    const uint32_t aBase = smem_u32(As);
    const uint32_t bBase = smem_u32(Bs);
    static constexpr size_t ROWSTEP = (size_t)32 * K_TOTAL;          // gmem: 32 rows
    static constexpr uint32_t SROWSTEP = 32 * TILE_K * 4;            // smem: 32 rows, bytes

    auto load_stage = [&](int pit) {
        const int s = pit & (STAGES - 1);
        const int kb = pit * TILE_K;
        const uint32_t ab = aBase + s * (A_STAGE_W * 4) + sOff;
        const uint32_t bb = bBase + s * (B_STAGE_W * 4) + sOff;
        #pragma unroll
        for (int i = 0; i < 4; i++) cp_async16(ab + i * SROWSTEP, aPtr + kb + i * ROWSTEP);
        #pragma unroll
        for (int i = 0; i < 8; i++) cp_async16(bb + i * SROWSTEP, bPtr + kb + i * ROWSTEP);
    };

    float acc[4][8][4];
    #pragma unroll
    for (int mt = 0; mt < 4; mt++)
        #pragma unroll
        for (int nt = 0; nt < 8; nt++)
            #pragma unroll
            for (int c = 0; c < 4; c++) acc[mt][nt][c] = 0.f;

    // prologue: stages 0..2
    #pragma unroll
    for (int s = 0; s < STAGES - 1; s++) { load_stage(s); cp_commit(); }

    #pragma unroll 1
    for (int it = 0; it < N_ITERS; ++it) {
        asm volatile("cp.async.wait_group %0;" :: "n"(STAGES - 2) : "memory");
        __syncthreads();

        // prefetch next stage (writes buffer (it+3)&3 == (it-1)&3, freed by the sync)
        const int pit = it + STAGES - 1;
        if (pit < N_ITERS) load_stage(pit);
        cp_commit();

        const int s = it & (STAGES - 1);
        const float* A = As + s * A_STAGE_W;
        const float* B = Bs + s * B_STAGE_W;

        #pragma unroll
        for (int kk = 0; kk < 4; kk++) {
            const int k0 = kk * 8;
            const int cs = (k0 + tig) ^ (gid << 2);     // swizzled col (r&7 == gid)
            uint32_t afr[4][4], bfr[8][2];
            #pragma unroll
            for (int mt = 0; mt < 4; mt++) {
                const uint32_t* Ar = (const uint32_t*)(A + (wm + mt * 16 + gid) * TILE_K);
                afr[mt][0] = Ar[cs];
                afr[mt][1] = Ar[cs + 8 * TILE_K];
                afr[mt][2] = Ar[cs ^ 4];
                afr[mt][3] = Ar[(cs ^ 4) + 8 * TILE_K];
            }
            #pragma unroll
            for (int nt = 0; nt < 8; nt++) {
                const uint32_t* Br = (const uint32_t*)(B + (wn + nt * 8 + gid) * TILE_K);
                bfr[nt][0] = Br[cs];
                bfr[nt][1] = Br[cs ^ 4];
            }
            #pragma unroll
            for (int mt = 0; mt < 4; mt++)
                #pragma unroll
                for (int nt = 0; nt < 8; nt++)
                    mma_tf32(acc[mt][nt], afr[mt], bfr[nt]);
        }
    }

    // ---- epilogue: direct gmem store + bias ----
    #pragma unroll
    for (int nt = 0; nt < 8; nt++) {
        const int n = n0 + wn + nt * 8 + tig * 2;
        const float bv0 = __ldg(bias + n);
        const float bv1 = __ldg(bias + n + 1);
        #pragma unroll
        for (int mt = 0; mt < 4; mt++) {
            const int m = m0 + wm + mt * 16 + gid;
            float2 v0 = { acc[mt][nt][0] + bv0, acc[mt][nt][1] + bv1 };
            float2 v1 = { acc[mt][nt][2] + bv0, acc[mt][nt][3] + bv1 };
            *(float2*)(out + (size_t)m * N_TOTAL + n) = v0;
            *(float2*)(out + (size_t)(m + 8) * N_TOTAL + n) = v1;
        }
    }
}

// ---------------- launch ----------------
extern "C" void kernel_launch(void* const* d_in, const int* in_sizes, int n_in,
                              void* d_out, int out_size) {
    const float* x     = (const float*)d_in[0];
    const int*   wp    = (const int*)d_in[1];
    const float* scale = (const float*)d_in[2];
    const float* zp    = (const float*)d_in[3];
    const float* bias  = (const float*)d_in[4];
    float* out = (float*)d_out;

    cudaFuncSetAttribute(gemm_kernel,
                         cudaFuncAttributeMaxDynamicSharedMemorySize, SMEM_BYTES);

    dequant_kernel<<<(N_TOTAL * PACKED) / 256, 256>>>(wp, scale, zp);
    xprep_kernel<<<(M_TOTAL * K_TOTAL / 4) / 256, 256>>>(x);
    gemm_kernel<<<GRID, THREADS, SMEM_BYTES>>>(bias, out);
}

// round 9
// speedup vs baseline: 2.1426x; 1.9314x over previous
#include <cuda_runtime.h>
#include <cuda_fp16.h>
#include <cstdint>
#include <cstddef>

#define DINL __device__ __forceinline__

// ---------------- problem constants ----------------
static constexpr int M_TOTAL = 8192;
static constexpr int N_TOTAL = 11008;
static constexpr int K_TOTAL = 4096;
static constexpr int PACKED  = K_TOTAL / 2;
static constexpr int NGROUPS = 32;

static constexpr int TILE_M = 128;
static constexpr int TILE_N = 256;
static constexpr int TILE_K = 64;                     // halves (= 128B per row)
static constexpr int STAGES = 4;
static constexpr int N_ITERS = K_TOTAL / TILE_K;      // 64
static constexpr int THREADS = 256;

static constexpr int NUM_MT = M_TOTAL / TILE_M;       // 64
static constexpr int NUM_NT = N_TOTAL / TILE_N;       // 43
static constexpr int GRID   = NUM_MT * NUM_NT;        // 2752
static constexpr int GROUP_M = 12;

static constexpr int A_STAGE_H = TILE_M * TILE_K;     // 8192 halves = 16KB
static constexpr int B_STAGE_H = TILE_N * TILE_K;     // 16384 halves = 32KB
static constexpr int SMEM_BYTES = STAGES * (A_STAGE_H + B_STAGE_H) * 2;   // 196608

// ---------------- persistent scratch (fp16) ----------------
__device__ __half g_W[(size_t)N_TOTAL * K_TOTAL];
__device__ __half g_X[(size_t)M_TOTAL * K_TOTAL];

// ---------------- helpers ----------------
DINL uint32_t smem_u32(const void* p) {
    uint32_t a;
    asm("{ .reg .u64 t; cvta.to.shared.u64 t, %1; cvt.u32.u64 %0, t; }" : "=r"(a) : "l"(p));
    return a;
}
DINL void cp_async16(uint32_t dst, const void* src) {
    asm volatile("cp.async.cg.shared.global [%0], [%1], 16;" :: "r"(dst), "l"(src) : "memory");
}
DINL void cp_commit() { asm volatile("cp.async.commit_group;" ::: "memory"); }

// m16n8k16 fp16 MMA with fp32 accumulate
DINL void mma_f16(float* d, const uint32_t* a, const uint32_t* b) {
    asm volatile(
        "mma.sync.aligned.m16n8k16.row.col.f32.f16.f16.f32 "
        "{%0,%1,%2,%3}, {%4,%5,%6,%7}, {%8,%9}, {%0,%1,%2,%3};"
        : "+f"(d[0]), "+f"(d[1]), "+f"(d[2]), "+f"(d[3])
        : "r"(a[0]), "r"(a[1]), "r"(a[2]), "r"(a[3]), "r"(b[0]), "r"(b[1]));
}

// ---------------- prep kernels ----------------
__global__ void dequant_kernel(const int* __restrict__ wp,
                               const float* __restrict__ scale,
                               const float* __restrict__ zp) {
    size_t idx = (size_t)blockIdx.x * blockDim.x + threadIdx.x;   // over O * PACKED
    int o = (int)(idx >> 11);
    int p = (int)(idx & 2047);
    int v  = wp[idx];
    int hi = (v >> 4) & 15;          // high nibble first
    int lo = v & 15;
    int g  = p >> 6;
    float s = scale[o * NGROUPS + g];
    float z = zp[o * NGROUPS + g];
    __half2 out;
    out.x = __float2half_rn(((float)hi - z) * s);
    out.y = __float2half_rn(((float)lo - z) * s);
    *(__half2*)(g_W + (size_t)o * K_TOTAL + 2 * p) = out;
}

__global__ void xprep_kernel(const float* __restrict__ x) {
    size_t i = (size_t)blockIdx.x * blockDim.x + threadIdx.x;     // over M*K/4
    float4 v = ((const float4*)x)[i];
    __half2 h0 = { __float2half_rn(v.x), __float2half_rn(v.y) };
    __half2 h1 = { __float2half_rn(v.z), __float2half_rn(v.w) };
    *(__half2*)(g_X + 4 * i)     = h0;
    *(__half2*)(g_X + 4 * i + 2) = h1;
}

// ---------------- FP16 mma.sync GEMM, 128x256 CTA, 64x64 warp ----------------
__global__ void __launch_bounds__(THREADS, 1)
gemm_kernel(const float* __restrict__ bias, float* __restrict__ out) {
    extern __shared__ __half smem[];
    __half* As = smem;                            // [STAGES][8192]
    __half* Bs = smem + STAGES * A_STAGE_H;       // [STAGES][16384]

    const int tid  = threadIdx.x;
    const int lane = tid & 31;
    const int wid  = tid >> 5;
    const int wm   = (wid & 1) * 64;     // warp M offset (2 rows of warps)
    const int wn   = (wid >> 1) * 64;    // warp N offset (4 cols of warps)
    const int tig  = lane & 3;
    const int gid  = lane >> 2;

    // ---- supergroup rasterization ----
    int bid = blockIdx.x;
    int group = bid / (GROUP_M * NUM_NT);
    int rem   = bid % (GROUP_M * NUM_NT);
    int gm    = NUM_MT - group * GROUP_M;
    if (gm > GROUP_M) gm = GROUP_M;
    const int m0 = (group * GROUP_M + rem % gm) * TILE_M;
    const int n0 = (rem / gm) * TILE_N;

    // ---- cp.async addressing ----
    // rows are 64 halves = 128B = 8 chunks of 16B. chunk' = chunk ^ (row & 7).
    // A: 1024 chunks (4/thread), B: 2048 (8/thread); slot i = row + 32*i.
    const int lrow = tid >> 3;           // 0..31
    const int lch  = tid & 7;            // 0..7
    const __half* aPtr = g_X + (size_t)(m0 + lrow) * K_TOTAL + lch * 8;
    const __half* bPtr = g_W + (size_t)(n0 + lrow) * K_TOTAL + lch * 8;
    const uint32_t sOff = (uint32_t)(lrow * 128 + 16 * (lch ^ (lrow & 7)));  // bytes
    const uint32_t aBase = smem_u32(As);
    const uint32_t bBase = smem_u32(Bs);
    static constexpr size_t ROWSTEP  = (size_t)32 * K_TOTAL;   // gmem halves: 32 rows
    static constexpr uint32_t SROWSTEP = 32 * 128;             // smem bytes: 32 rows

    auto load_stage = [&](int pit) {
        const int s = pit & (STAGES - 1);
        const int kb = pit * TILE_K;
        const uint32_t ab = aBase + s * (A_STAGE_H * 2) + sOff;
        const uint32_t bb = bBase + s * (B_STAGE_H * 2) + sOff;
        #pragma unroll
        for (int i = 0; i < 4; i++) cp_async16(ab + i * SROWSTEP, aPtr + kb + i * ROWSTEP);
        #pragma unroll
        for (int i = 0; i < 8; i++) cp_async16(bb + i * SROWSTEP, bPtr + kb + i * ROWSTEP);
    };

    float acc[4][8][4];
    #pragma unroll
    for (int mt = 0; mt < 4; mt++)
        #pragma unroll
        for (int nt = 0; nt < 8; nt++)
            #pragma unroll
            for (int c = 0; c < 4; c++) acc[mt][nt][c] = 0.f;

    // prologue: stages 0..2
    #pragma unroll
    for (int s = 0; s < STAGES - 1; s++) { load_stage(s); cp_commit(); }

    #pragma unroll 1
    for (int it = 0; it < N_ITERS; ++it) {
        asm volatile("cp.async.wait_group %0;" :: "n"(STAGES - 2) : "memory");
        __syncthreads();

        const int pit = it + STAGES - 1;
        if (pit < N_ITERS) load_stage(pit);
        cp_commit();

        const int s = it & (STAGES - 1);
        const __half* A = As + s * A_STAGE_H;
        const __half* B = Bs + s * B_STAGE_H;

        #pragma unroll
        for (int kk = 0; kk < 4; kk++) {
            // word indices within a 32-word (128B) row; rows in a warp all have row&7 == gid
            const int cs0 = tig | ((((2 * kk)     ^ gid) & 7) << 2);  // k halves k0+2tig..+1
            const int cs1 = tig | ((((2 * kk + 1) ^ gid) & 7) << 2);  // k halves k0+2tig+8..+9
            uint32_t afr[4][4], bfr[8][2];
            #pragma unroll
            for (int mt = 0; mt < 4; mt++) {
                const uint32_t* Ar  = (const uint32_t*)(A + (wm + mt * 16 + gid) * TILE_K);
                const uint32_t* Ar8 = (const uint32_t*)(A + (wm + mt * 16 + gid + 8) * TILE_K);
                afr[mt][0] = Ar[cs0];
                afr[mt][1] = Ar8[cs0];
                afr[mt][2] = Ar[cs1];
                afr[mt][3] = Ar8[cs1];
            }
            #pragma unroll
            for (int nt = 0; nt < 8; nt++) {
                const uint32_t* Br = (const uint32_t*)(B + (wn + nt * 8 + gid) * TILE_K);
                bfr[nt][0] = Br[cs0];
                bfr[nt][1] = Br[cs1];
            }
            #pragma unroll
            for (int mt = 0; mt < 4; mt++)
                #pragma unroll
                for (int nt = 0; nt < 8; nt++)
                    mma_f16(acc[mt][nt], afr[mt], bfr[nt]);
        }
    }

    // ---- epilogue: direct gmem store + bias (D layout same as tf32 k8) ----
    #pragma unroll
    for (int nt = 0; nt < 8; nt++) {
        const int n = n0 + wn + nt * 8 + tig * 2;
        const float bv0 = __ldg(bias + n);
        const float bv1 = __ldg(bias + n + 1);
        #pragma unroll
        for (int mt = 0; mt < 4; mt++) {
            const int m = m0 + wm + mt * 16 + gid;
            float2 v0 = { acc[mt][nt][0] + bv0, acc[mt][nt][1] + bv1 };
            float2 v1 = { acc[mt][nt][2] + bv0, acc[mt][nt][3] + bv1 };
            *(float2*)(out + (size_t)m * N_TOTAL + n) = v0;
            *(float2*)(out + (size_t)(m + 8) * N_TOTAL + n) = v1;
        }
    }
}

// ---------------- launch ----------------
extern "C" void kernel_launch(void* const* d_in, const int* in_sizes, int n_in,
                              void* d_out, int out_size) {
    const float* x     = (const float*)d_in[0];
    const int*   wp    = (const int*)d_in[1];
    const float* scale = (const float*)d_in[2];
    const float* zp    = (const float*)d_in[3];
    const float* bias  = (const float*)d_in[4];
    float* out = (float*)d_out;

    cudaFuncSetAttribute(gemm_kernel,
                         cudaFuncAttributeMaxDynamicSharedMemorySize, SMEM_BYTES);

    dequant_kernel<<<(N_TOTAL * PACKED) / 256, 256>>>(wp, scale, zp);
    xprep_kernel<<<(M_TOTAL * K_TOTAL / 4) / 256, 256>>>(x);
    gemm_kernel<<<GRID, THREADS, SMEM_BYTES>>>(bias, out);
}

// round 11
// speedup vs baseline: 2.2317x; 1.0416x over previous
#include <cuda_runtime.h>
#include <cuda_fp16.h>
#include <cstdint>
#include <cstddef>

#define DINL __device__ __forceinline__

// ---------------- problem constants ----------------
static constexpr int M_TOTAL = 8192;
static constexpr int N_TOTAL = 11008;
static constexpr int K_TOTAL = 4096;
static constexpr int NGROUPS = 32;

static constexpr int TILE_M = 128;
static constexpr int TILE_N = 256;
static constexpr int TILE_K = 64;                     // halves = 128B per row
static constexpr int STAGES = 4;
static constexpr int N_ITERS = K_TOTAL / TILE_K;      // 64
static constexpr int THREADS = 256;

static constexpr int NUM_MT = M_TOTAL / TILE_M;       // 64
static constexpr int NUM_NT = N_TOTAL / TILE_N;       // 43
static constexpr int GRID   = NUM_MT * NUM_NT;        // 2752
static constexpr int GROUP_M = 12;

static constexpr int A_STAGE_H = TILE_M * TILE_K;     // 8192 halves = 16KB
static constexpr int B_STAGE_H = TILE_N * TILE_K;     // 16384 halves = 32KB
static constexpr int SMEM_BYTES = STAGES * (A_STAGE_H + B_STAGE_H) * 2;   // 196608

// ---------------- persistent scratch (fp16) ----------------
__device__ __half g_W[(size_t)N_TOTAL * K_TOTAL];
__device__ __half g_X[(size_t)M_TOTAL * K_TOTAL];

// ---------------- helpers ----------------
DINL uint32_t smem_u32(const void* p) {
    uint32_t a;
    asm("{ .reg .u64 t; cvta.to.shared.u64 t, %1; cvt.u32.u64 %0, t; }" : "=r"(a) : "l"(p));
    return a;
}
DINL void cp_async16(uint32_t dst, const void* src) {
    asm volatile("cp.async.cg.shared.global [%0], [%1], 16;" :: "r"(dst), "l"(src) : "memory");
}
DINL void cp_commit() { asm volatile("cp.async.commit_group;" ::: "memory"); }

DINL void mma_f16(float* d, const uint32_t* a, const uint32_t* b) {
    asm volatile(
        "mma.sync.aligned.m16n8k16.row.col.f32.f16.f16.f32 "
        "{%0,%1,%2,%3}, {%4,%5,%6,%7}, {%8,%9}, {%0,%1,%2,%3};"
        : "+f"(d[0]), "+f"(d[1]), "+f"(d[2]), "+f"(d[3])
        : "r"(a[0]), "r"(a[1]), "r"(a[2]), "r"(a[3]), "r"(b[0]), "r"(b[1]));
}

DINL void ldsm4(uint32_t* r, uint32_t addr) {
    asm volatile("ldmatrix.sync.aligned.m8n8.x4.shared.b16 {%0,%1,%2,%3}, [%4];"
                 : "=r"(r[0]), "=r"(r[1]), "=r"(r[2]), "=r"(r[3]) : "r"(addr));
}

// ---------------- prep kernels ----------------
// vectorized: 4 packed int32 -> 8 fp16 per thread (16B load, 16B store)
__global__ void dequant_kernel(const int* __restrict__ wp,
                               const float* __restrict__ scale,
                               const float* __restrict__ zp) {
    size_t idx = (size_t)blockIdx.x * blockDim.x + threadIdx.x;   // over O * 512
    int o  = (int)(idx >> 9);
    int pc = (int)(idx & 511);           // int4-chunk within row
    int4 v = ((const int4*)wp)[idx];
    int g  = pc >> 4;                    // 16 chunks per group
    float s = scale[o * NGROUPS + g];
    float z = zp[o * NGROUPS + g];
    __half2 h[4];
    int vv[4] = { v.x, v.y, v.z, v.w };
    #pragma unroll
    for (int i = 0; i < 4; i++) {
        int hi = (vv[i] >> 4) & 15;      // high nibble first
        int lo = vv[i] & 15;
        h[i].x = __float2half_rn(((float)hi - z) * s);
        h[i].y = __float2half_rn(((float)lo - z) * s);
    }
    *(uint4*)(g_W + (size_t)o * K_TOTAL + pc * 8) = *(uint4*)h;
}

__global__ void xprep_kernel(const float* __restrict__ x) {
    size_t i = (size_t)blockIdx.x * blockDim.x + threadIdx.x;     // over M*K/4
    float4 v = ((const float4*)x)[i];
    __half2 h0 = { __float2half_rn(v.x), __float2half_rn(v.y) };
    __half2 h1 = { __float2half_rn(v.z), __float2half_rn(v.w) };
    *(__half2*)(g_X + 4 * i)     = h0;
    *(__half2*)(g_X + 4 * i + 2) = h1;
}

// ---------------- FP16 mma.sync GEMM, 128x256 CTA, 64x64 warp, ldmatrix ----------------
__global__ void __launch_bounds__(THREADS, 1)
gemm_kernel(const float* __restrict__ bias, float* __restrict__ out) {
    extern __shared__ __half smem[];
    __half* As = smem;                            // [STAGES][8192]
    __half* Bs = smem + STAGES * A_STAGE_H;       // [STAGES][16384]

    const int tid  = threadIdx.x;
    const int lane = tid & 31;
    const int wid  = tid >> 5;
    const int wm   = (wid & 1) * 64;
    const int wn   = (wid >> 1) * 64;
    const int tig  = lane & 3;
    const int gid  = lane >> 2;

    // ---- supergroup rasterization ----
    int bid = blockIdx.x;
    int group = bid / (GROUP_M * NUM_NT);
    int rem   = bid % (GROUP_M * NUM_NT);
    int gm    = NUM_MT - group * GROUP_M;
    if (gm > GROUP_M) gm = GROUP_M;
    const int m0 = (group * GROUP_M + rem % gm) * TILE_M;
    const int n0 = (rem / gm) * TILE_N;

    // ---- cp.async addressing (rows = 128B, chunk' = chunk ^ (row&7)) ----
    const int lrow = tid >> 3;
    const int lch  = tid & 7;
    const __half* aPtr = g_X + (size_t)(m0 + lrow) * K_TOTAL + lch * 8;
    const __half* bPtr = g_W + (size_t)(n0 + lrow) * K_TOTAL + lch * 8;
    const uint32_t sOff = (uint32_t)(lrow * 128 + 16 * (lch ^ (lrow & 7)));
    const uint32_t aBase = smem_u32(As);
    const uint32_t bBase = smem_u32(Bs);
    static constexpr size_t ROWSTEP   = (size_t)32 * K_TOTAL;
    static constexpr uint32_t SROWSTEP = 32 * 128;

    auto load_stage = [&](int pit) {
        const int s = pit & (STAGES - 1);
        const int kb = pit * TILE_K;
        const uint32_t ab = aBase + s * (A_STAGE_H * 2) + sOff;
        const uint32_t bb = bBase + s * (B_STAGE_H * 2) + sOff;
        #pragma unroll
        for (int i = 0; i < 4; i++) cp_async16(ab + i * SROWSTEP, aPtr + kb + i * ROWSTEP);
        #pragma unroll
        for (int i = 0; i < 8; i++) cp_async16(bb + i * SROWSTEP, bPtr + kb + i * ROWSTEP);
    };

    // ---- ldmatrix per-lane address setup ----
    const int l7 = lane & 7;
    // A x4: matrices (m0..7,k0),(m8..15,k0),(m0..7,k8),(m8..15,k8)
    const int aSel  = lane >> 3;
    const int aMoff = (aSel & 1) * 8 + l7;
    const int aKblk = aSel >> 1;                 // 0/1 (which 16B k-block)
    uint32_t aRow[4];
    #pragma unroll
    for (int mt = 0; mt < 4; mt++)
        aRow[mt] = (uint32_t)(wm + mt * 16 + aMoff) * 128;
    // B x4: matrices (nt_even,k0),(nt_even,k1),(nt_odd,k0),(nt_odd,k1)
    const int bNoff = ((lane >> 4) << 3) + l7;
    const int bKblk = (lane >> 3) & 1;
    uint32_t bRow[4];
    #pragma unroll
    for (int ntp = 0; ntp < 4; ntp++)
        bRow[ntp] = (uint32_t)(wn + ntp * 16 + bNoff) * 128;

    float acc[4][8][4];
    #pragma unroll
    for (int mt = 0; mt < 4; mt++)
        #pragma unroll
        for (int nt = 0; nt < 8; nt++)
            #pragma unroll
            for (int c = 0; c < 4; c++) acc[mt][nt][c] = 0.f;

    uint32_t afr[2][4][4];     // [buf][mt][4]
    uint32_t bfr[2][4][4];     // [buf][ntp][4] = (nt_e k0, nt_e k1, nt_o k0, nt_o k1)

    // prologue
    #pragma unroll
    for (int s = 0; s < STAGES - 1; s++) { load_stage(s); cp_commit(); }

    #pragma unroll 1
    for (int it = 0; it < N_ITERS; ++it) {
        asm volatile("cp.async.wait_group %0;" :: "n"(STAGES - 2) : "memory");
        __syncthreads();

        const int s = it & (STAGES - 1);
        const uint32_t aStage = aBase + s * (A_STAGE_H * 2);
        const uint32_t bStage = bBase + s * (B_STAGE_H * 2);

        // fragments for kk=0
        {
            const uint32_t ac = 16u * ((uint32_t)(0 + aKblk) ^ l7);
            const uint32_t bc = 16u * ((uint32_t)(0 + bKblk) ^ l7);
            #pragma unroll
            for (int mt = 0; mt < 4; mt++)  ldsm4(afr[0][mt],  aStage + aRow[mt]  + ac);
            #pragma unroll
            for (int ntp = 0; ntp < 4; ntp++) ldsm4(bfr[0][ntp], bStage + bRow[ntp] + bc);
        }

        // prefetch next gmem stage
        const int pit = it + STAGES - 1;
        if (pit < N_ITERS) load_stage(pit);
        cp_commit();

        #pragma unroll
        for (int kk = 0; kk < 4; kk++) {
            const int cur = kk & 1, nxt = cur ^ 1;
            if (kk < 3) {
                const uint32_t ac = 16u * ((uint32_t)(2 * (kk + 1) + aKblk) ^ l7);
                const uint32_t bc = 16u * ((uint32_t)(2 * (kk + 1) + bKblk) ^ l7);
                #pragma unroll
                for (int mt = 0; mt < 4; mt++)  ldsm4(afr[nxt][mt],  aStage + aRow[mt]  + ac);
                #pragma unroll
                for (int ntp = 0; ntp < 4; ntp++) ldsm4(bfr[nxt][ntp], bStage + bRow[ntp] + bc);
            }
            #pragma unroll
            for (int mt = 0; mt < 4; mt++)
                #pragma unroll
                for (int nt = 0; nt < 8; nt++)
                    mma_f16(acc[mt][nt], afr[cur][mt], &bfr[cur][nt >> 1][(nt & 1) * 2]);
        }
    }

    // ---- epilogue: direct gmem store + bias ----
    #pragma unroll
    for (int nt = 0; nt < 8; nt++) {
        const int n = n0 + wn + nt * 8 + tig * 2;
        const float bv0 = __ldg(bias + n);
        const float bv1 = __ldg(bias + n + 1);
        #pragma unroll
        for (int mt = 0; mt < 4; mt++) {
            const int m = m0 + wm + mt * 16 + gid;
            float2 v0 = { acc[mt][nt][0] + bv0, acc[mt][nt][1] + bv1 };
            float2 v1 = { acc[mt][nt][2] + bv0, acc[mt][nt][3] + bv1 };
            *(float2*)(out + (size_t)m * N_TOTAL + n) = v0;
            *(float2*)(out + (size_t)(m + 8) * N_TOTAL + n) = v1;
        }
    }
}

// ---------------- launch ----------------
extern "C" void kernel_launch(void* const* d_in, const int* in_sizes, int n_in,
                              void* d_out, int out_size) {
    const float* x     = (const float*)d_in[0];
    const int*   wp    = (const int*)d_in[1];
    const float* scale = (const float*)d_in[2];
    const float* zp    = (const float*)d_in[3];
    const float* bias  = (const float*)d_in[4];
    float* out = (float*)d_out;

    cudaFuncSetAttribute(gemm_kernel,
                         cudaFuncAttributeMaxDynamicSharedMemorySize, SMEM_BYTES);

    dequant_kernel<<<(N_TOTAL * 512) / 256, 256>>>(wp, scale, zp);   // 22016 blocks
    xprep_kernel<<<(M_TOTAL * K_TOTAL / 4) / 256, 256>>>(x);
    gemm_kernel<<<GRID, THREADS, SMEM_BYTES>>>(bias, out);
}

// round 17
// speedup vs baseline: 2.4244x; 1.0864x over previous
#include <cuda_runtime.h>
#include <cuda_fp16.h>
#include <cstdint>
#include <cstddef>

#define DINL __device__ __forceinline__

// ---------------- problem constants ----------------
static constexpr int M_TOTAL = 8192;
static constexpr int N_TOTAL = 11008;
static constexpr int K_TOTAL = 4096;
static constexpr int NGROUPS = 32;

static constexpr int TILE_M = 128;
static constexpr int TILE_N = 128;
static constexpr int TILE_K = 64;                     // halves = 128B per row
static constexpr int STAGES = 3;
static constexpr int N_ITERS = K_TOTAL / TILE_K;      // 64
static constexpr int THREADS = 256;

static constexpr int NUM_MT = M_TOTAL / TILE_M;       // 64
static constexpr int NUM_NT = N_TOTAL / TILE_N;       // 86
static constexpr int GRID   = NUM_MT * NUM_NT;        // 5504
static constexpr int GROUP_M = 16;

static constexpr int A_STAGE_H = TILE_M * TILE_K;     // 8192 halves = 16KB
static constexpr int B_STAGE_H = TILE_N * TILE_K;     // 8192 halves = 16KB
static constexpr int SMEM_BYTES = STAGES * (A_STAGE_H + B_STAGE_H) * 2;   // 98304

// ---------------- persistent scratch (fp16) ----------------
__device__ __half g_W[(size_t)N_TOTAL * K_TOTAL];
__device__ __half g_X[(size_t)M_TOTAL * K_TOTAL];

// ---------------- helpers ----------------
DINL uint32_t smem_u32(const void* p) {
    uint32_t a;
    asm("{ .reg .u64 t; cvta.to.shared.u64 t, %1; cvt.u32.u64 %0, t; }" : "=r"(a) : "l"(p));
    return a;
}
DINL void cp_async16(uint32_t dst, const void* src) {
    asm volatile("cp.async.cg.shared.global [%0], [%1], 16;" :: "r"(dst), "l"(src) : "memory");
}
DINL void cp_commit() { asm volatile("cp.async.commit_group;" ::: "memory"); }

DINL void mma_f16(float* d, const uint32_t* a, const uint32_t* b) {
    asm volatile(
        "mma.sync.aligned.m16n8k16.row.col.f32.f16.f16.f32 "
        "{%0,%1,%2,%3}, {%4,%5,%6,%7}, {%8,%9}, {%0,%1,%2,%3};"
        : "+f"(d[0]), "+f"(d[1]), "+f"(d[2]), "+f"(d[3])
        : "r"(a[0]), "r"(a[1]), "r"(a[2]), "r"(a[3]), "r"(b[0]), "r"(b[1]));
}

DINL void ldsm4(uint32_t* r, uint32_t addr) {
    asm volatile("ldmatrix.sync.aligned.m8n8.x4.shared.b16 {%0,%1,%2,%3}, [%4];"
                 : "=r"(r[0]), "=r"(r[1]), "=r"(r[2]), "=r"(r[3]) : "r"(addr));
}

// ---------------- prep kernels ----------------
__global__ void dequant_kernel(const int* __restrict__ wp,
                               const float* __restrict__ scale,
                               const float* __restrict__ zp) {
    size_t idx = (size_t)blockIdx.x * blockDim.x + threadIdx.x;   // over O * 512
    int o  = (int)(idx >> 9);
    int pc = (int)(idx & 511);
    int4 v = ((const int4*)wp)[idx];
    int g  = pc >> 4;
    float s = scale[o * NGROUPS + g];
    float z = zp[o * NGROUPS + g];
    __half2 h[4];
    int vv[4] = { v.x, v.y, v.z, v.w };
    #pragma unroll
    for (int i = 0; i < 4; i++) {
        int hi = (vv[i] >> 4) & 15;      // high nibble first
        int lo = vv[i] & 15;
        h[i].x = __float2half_rn(((float)hi - z) * s);
        h[i].y = __float2half_rn(((float)lo - z) * s);
    }
    *(uint4*)(g_W + (size_t)o * K_TOTAL + pc * 8) = *(uint4*)h;
}

__global__ void xprep_kernel(const float* __restrict__ x) {
    size_t i = (size_t)blockIdx.x * blockDim.x + threadIdx.x;     // over M*K/4
    float4 v = ((const float4*)x)[i];
    __half2 h0 = { __float2half_rn(v.x), __float2half_rn(v.y) };
    __half2 h1 = { __float2half_rn(v.z), __float2half_rn(v.w) };
    *(__half2*)(g_X + 4 * i)     = h0;
    *(__half2*)(g_X + 4 * i + 2) = h1;
}

// ------- FP16 mma.sync GEMM, 128x128 CTA, 64x32 warp, 2 CTAs/SM -------
__global__ void __launch_bounds__(THREADS, 2)
gemm_kernel(const float* __restrict__ bias, float* __restrict__ out) {
    extern __shared__ __half smem[];
    __half* As = smem;                            // [STAGES][8192]
    __half* Bs = smem + STAGES * A_STAGE_H;       // [STAGES][8192]

    const int tid  = threadIdx.x;
    const int lane = tid & 31;
    const int wid  = tid >> 5;
    const int wm   = (wid & 1) * 64;     // 2 warp-rows
    const int wn   = (wid >> 1) * 32;    // 4 warp-cols
    const int tig  = lane & 3;
    const int gid  = lane >> 2;

    // ---- supergroup rasterization ----
    int bid = blockIdx.x;
    int group = bid / (GROUP_M * NUM_NT);
    int rem   = bid % (GROUP_M * NUM_NT);
    int gm    = NUM_MT - group * GROUP_M;
    if (gm > GROUP_M) gm = GROUP_M;
    const int m0 = (group * GROUP_M + rem % gm) * TILE_M;
    const int n0 = (rem / gm) * TILE_N;

    // ---- cp.async addressing (rows = 128B, chunk' = chunk ^ (row&7)) ----
    // A: 1024 chunks (4/thread), B: 1024 (4/thread); slot i = row + 32*i.
    const int lrow = tid >> 3;
    const int lch  = tid & 7;
    const __half* aPtr = g_X + (size_t)(m0 + lrow) * K_TOTAL + lch * 8;
    const __half* bPtr = g_W + (size_t)(n0 + lrow) * K_TOTAL + lch * 8;
    const uint32_t sOff = (uint32_t)(lrow * 128 + 16 * (lch ^ (lrow & 7)));
    const uint32_t aBase = smem_u32(As);
    const uint32_t bBase = smem_u32(Bs);
    static constexpr size_t ROWSTEP   = (size_t)32 * K_TOTAL;
    static constexpr uint32_t SROWSTEP = 32 * 128;

    auto load_stage = [&](int pit) {
        const int s = pit % STAGES;
        const int kb = pit * TILE_K;
        const uint32_t ab = aBase + s * (A_STAGE_H * 2) + sOff;
        const uint32_t bb = bBase + s * (B_STAGE_H * 2) + sOff;
        #pragma unroll
        for (int i = 0; i < 4; i++) cp_async16(ab + i * SROWSTEP, aPtr + kb + i * ROWSTEP);
        #pragma unroll
        for (int i = 0; i < 4; i++) cp_async16(bb + i * SROWSTEP, bPtr + kb + i * ROWSTEP);
    };

    // ---- ldmatrix per-lane address setup ----
    const int l7 = lane & 7;
    // A x4: (m0..7,k0),(m8..15,k0),(m0..7,k8),(m8..15,k8)
    const int aSel  = lane >> 3;
    const int aMoff = (aSel & 1) * 8 + l7;
    const int aKblk = aSel >> 1;
    uint32_t aRow[4];
    #pragma unroll
    for (int mt = 0; mt < 4; mt++)
        aRow[mt] = (uint32_t)(wm + mt * 16 + aMoff) * 128;
    // B x4: (nt_e,k0),(nt_e,k1),(nt_o,k0),(nt_o,k1)
    const int bNoff = ((lane >> 4) << 3) + l7;
    const int bKblk = (lane >> 3) & 1;
    uint32_t bRow[2];
    #pragma unroll
    for (int ntp = 0; ntp < 2; ntp++)
        bRow[ntp] = (uint32_t)(wn + ntp * 16 + bNoff) * 128;

    float acc[4][4][4];
    #pragma unroll
    for (int mt = 0; mt < 4; mt++)
        #pragma unroll
        for (int nt = 0; nt < 4; nt++)
            #pragma unroll
            for (int c = 0; c < 4; c++) acc[mt][nt][c] = 0.f;

    // prologue: stages 0..1
    #pragma unroll
    for (int s = 0; s < STAGES - 1; s++) { load_stage(s); cp_commit(); }

    #pragma unroll 1
    for (int it = 0; it < N_ITERS; ++it) {
        asm volatile("cp.async.wait_group %0;" :: "n"(STAGES - 2) : "memory");
        __syncthreads();

        // prefetch next gmem stage early
        const int pit = it + STAGES - 1;
        if (pit < N_ITERS) load_stage(pit);
        cp_commit();

        const int s = it % STAGES;
        const uint32_t aStage = aBase + s * (A_STAGE_H * 2);
        const uint32_t bStage = bBase + s * (B_STAGE_H * 2);

        #pragma unroll
        for (int kk = 0; kk < 4; kk++) {
            const uint32_t ac = 16u * ((uint32_t)(2 * kk + aKblk) ^ l7);
            const uint32_t bc = 16u * ((uint32_t)(2 * kk + bKblk) ^ l7);
            uint32_t afr[4][4], bfr[2][4];
            #pragma unroll
            for (int mt = 0; mt < 4; mt++)  ldsm4(afr[mt],  aStage + aRow[mt]  + ac);
            #pragma unroll
            for (int ntp = 0; ntp < 2; ntp++) ldsm4(bfr[ntp], bStage + bRow[ntp] + bc);
            #pragma unroll
            for (int mt = 0; mt < 4; mt++)
                #pragma unroll
                for (int nt = 0; nt < 4; nt++)
                    mma_f16(acc[mt][nt], afr[mt], &bfr[nt >> 1][(nt & 1) * 2]);
        }
    }

    // ---- epilogue: direct gmem store + bias ----
    #pragma unroll
    for (int nt = 0; nt < 4; nt++) {
        const int n = n0 + wn + nt * 8 + tig * 2;
        const float bv0 = __ldg(bias + n);
        const float bv1 = __ldg(bias + n + 1);
        #pragma unroll
        for (int mt = 0; mt < 4; mt++) {
            const int m = m0 + wm + mt * 16 + gid;
            float2 v0 = { acc[mt][nt][0] + bv0, acc[mt][nt][1] + bv1 };
            float2 v1 = { acc[mt][nt][2] + bv0, acc[mt][nt][3] + bv1 };
            *(float2*)(out + (size_t)m * N_TOTAL + n) = v0;
            *(float2*)(out + (size_t)(m + 8) * N_TOTAL + n) = v1;
        }
    }
}

// ---------------- launch ----------------
extern "C" void kernel_launch(void* const* d_in, const int* in_sizes, int n_in,
                              void* d_out, int out_size) {
    const float* x     = (const float*)d_in[0];
    const int*   wp    = (const int*)d_in[1];
    const float* scale = (const float*)d_in[2];
    const float* zp    = (const float*)d_in[3];
    const float* bias  = (const float*)d_in[4];
    float* out = (float*)d_out;

    cudaFuncSetAttribute(gemm_kernel,
                         cudaFuncAttributeMaxDynamicSharedMemorySize, SMEM_BYTES);

    dequant_kernel<<<(N_TOTAL * 512) / 256, 256>>>(wp, scale, zp);
    xprep_kernel<<<(M_TOTAL * K_TOTAL / 4) / 256, 256>>>(x);
    gemm_kernel<<<GRID, THREADS, SMEM_BYTES>>>(bias, out);
}